// round 13
// baseline (speedup 1.0000x reference)
#include <cuda_runtime.h>

// Cubic B-spline prefilter (Unser), DCT-II mirror boundaries, as a truncated
// symmetric FIR: h[k] = sqrt(3) * p^|k|, p = sqrt(3)-2, radius 6 (13 taps).
// R11 structure (best): occ-5-tuned kernels, scalar mirrored tile loads,
// in-place register-delay-line W filter. Single change vs R11: kWH now runs
// at occupancy 6 (6 x 37632 B = 225.8 KB smem/SM, reg cap 56).

#define NAX   192
#define KR    6
#define NT    (2*KR + 1)        // 13 taps
#define HALO  8                 // load halo (>= KR; keeps tile geometry)
#define TW    32                // strip output width
#define LC    (TW + 2*HALO)     // 48 loaded cols
#define P1    49                // smem pitch (odd -> conflict-free both ways)
#define SEGH  16                // H-phase outputs/thread
#define WLH   (SEGH + 2*KR)     // 28
#define SEGD  24
#define WLD   (SEGD + 2*KR)     // 36
#define TPBF  192
#define TPBD  256

// taps T[k] = sqrt(3)*p^|k-6| as compile-time floats -> FFMA-imm in SASS (rt=1)
#define DECL_TAPS const float T[NT] = { \
     6.4102556e-04f, -2.3923386e-03f,  8.9283341e-03f, -3.3320997e-02f, \
     1.2435565e-01f, -4.6410161e-01f,  1.7320508e+00f, -4.6410161e-01f, \
     1.2435565e-01f, -3.3320997e-02f,  8.9283341e-03f, -2.3923386e-03f, \
     6.4102556e-04f }

__device__ __forceinline__ int mirror_idx(int i) {
    i = (i < 0) ? (-1 - i) : i;                  // half-sample left reflect
    return (i >= NAX) ? (2 * NAX - 1 - i) : i;   // half-sample right reflect
}

// ---------------------------------------------------------------------------
// Fused W+H pass, one 192 x 32 strip per block, one 192x49 smem buffer.
// Phase 1: load 192x48 (w-halo mirrored), 48 independent coalesced LDG.
// Phase 2: W filter in place (thread = row, 13-deep register delay line).
// Phase 3: H filter on cols [8,40), direct coalesced STG.
// ---------------------------------------------------------------------------
__global__ __launch_bounds__(TPBF, 6) void kWH(const float* __restrict__ in,
                                               float* __restrict__ out) {
    extern __shared__ float s[];   // [192][P1]

    const int tid   = threadIdx.x;              // 0..191
    const int strip = blockIdx.x % (NAX / TW);  // 6 strips; adjacent -> L2 halo reuse
    const int slice = blockIdx.x / (NAX / TW);
    const int base  = slice * (NAX * NAX);
    const int wbase = strip * TW;

    // ---- load 192 x 48 (coalesced LDG, independent -> high MLP)
#pragma unroll
    for (int k = 0; k < (NAX * LC) / TPBF; ++k) {   // 48 iterations
        int i   = tid + TPBF * k;
        int row = i / LC;
        int c   = i - row * LC;
        s[row * P1 + c] = in[base + row * NAX + mirror_idx(wbase - HALO + c)];
    }
    __syncthreads();

    DECL_TAPS;

    // ---- W filter in place: thread owns row `tid`.
    // Output j needs smem cols (j+2)..(j+14); write col j+8 after reading
    // col j+14 -> later iterations read smem only at cols >= j+15. Safe.
    {
        float* rp = &s[tid * P1];   // lanes: stride-49 -> conflict-free
        float win[NT];
#pragma unroll
        for (int m = 0; m < NT - 1; ++m) win[m] = rp[2 + m];   // cols 2..13
#pragma unroll
        for (int j = 0; j < TW; ++j) {
            win[NT - 1] = rp[j + HALO + KR];                   // col j+14
            float acc = 0.0f;
#pragma unroll
            for (int k = 0; k < NT; ++k) acc = fmaf(T[k], win[k], acc);
            rp[j + HALO] = acc;                                // col j+8
#pragma unroll
            for (int m = 0; m < NT - 1; ++m) win[m] = win[m + 1];  // reg rotate
        }
    }
    __syncthreads();

    // ---- H filter: 384 tasks = (w 0..31) x (hseg 0..11 of 16 outputs)
#pragma unroll
    for (int r = 0; r < 2; ++r) {
        const int t    = tid + TPBF * r;
        const int w    = t & (TW - 1);
        const int hseg = t >> 5;                 // 0..11
        const int h0   = hseg * SEGH;

        float win[WLH];
#pragma unroll
        for (int m = 0; m < WLH; ++m)
            win[m] = s[mirror_idx(h0 - KR + m) * P1 + HALO + w];  // lane = w -> conflict-free

        float* o = out + base + wbase + w;
#pragma unroll
        for (int j = 0; j < SEGH; ++j) {
            float acc = 0.0f;
#pragma unroll
            for (int k = 0; k < NT; ++k) acc = fmaf(T[k], win[j + k], acc);
            o[(h0 + j) * NAX] = acc;             // 128B coalesced per j
        }
    }
}

// ---------------------------------------------------------------------------
// D pass (stride 192*192), in place. Tile: 192(d) x 32(w).  (unchanged)
// ---------------------------------------------------------------------------
__global__ __launch_bounds__(TPBD, 5) void kD(float* buf) {
    __shared__ float s[NAX][32];
    const int tid = threadIdx.x;
    const int c   = blockIdx.x % (NAX / 32);
    const int tt  = blockIdx.x / (NAX / 32);
    const int b   = tt / NAX;
    const int hh  = tt % NAX;
    const int base = b * (NAX * NAX * NAX) + hh * NAX + c * 32;

    const int w  = tid & 31;
    const int a4 = tid >> 5;
#pragma unroll
    for (int k = 0; k < NAX / 8; ++k)   // 24 outstanding LDG/thread
        s[a4 + 8 * k][w] = buf[base + (a4 + 8 * k) * (NAX * NAX) + w];
    __syncthreads();

    DECL_TAPS;
    const int a0 = (tid >> 5) * SEGD;
    float win[WLD];
#pragma unroll
    for (int m = 0; m < WLD; ++m)
        win[m] = s[mirror_idx(a0 - KR + m)][w];

#pragma unroll
    for (int j = 0; j < SEGD; ++j) {
        float acc = 0.0f;
#pragma unroll
        for (int k = 0; k < NT; ++k) acc = fmaf(T[k], win[j + k], acc);
        buf[base + (a0 + j) * (NAX * NAX) + w] = acc;     // 128B coalesced per j
    }
}

extern "C" void kernel_launch(void* const* d_in, const int* in_sizes, int n_in,
                              void* d_out, int out_size) {
    const float* x = (const float*)d_in[0];
    float* y = (float*)d_out;

    const int B = 8;   // 4 batch * 2 channel
    const int smemWH = NAX * P1 * (int)sizeof(float);   // 37632 B

    static int attr_set = 0;
    if (!attr_set) {
        cudaFuncSetAttribute(kWH, cudaFuncAttributeMaxDynamicSharedMemorySize, smemWH);
        attr_set = 1;
    }

    const int gridWH = B * NAX * (NAX / TW);   // 9216 blocks
    const int gridD  = B * NAX * (NAX / 32);   // 9216 blocks

    kWH<<<gridWH, TPBF, smemWH>>>(x, y);  // W+H fused: d_in -> d_out
    kD<<<gridD, TPBD>>>(y);               // D axis: in place
}

// round 14
// speedup vs baseline: 1.2139x; 1.2139x over previous
#include <cuda_runtime.h>
#include <cuda_fp16.h>

// Cubic B-spline prefilter (Unser), DCT-II mirror boundaries, as a truncated
// symmetric FIR: h[k] = sqrt(3) * p^|k|, p = sqrt(3)-2, radius 6 (13 taps).
// R11 structure (best operating point: occ 5, scalar mirrored tile loads,
// in-place register-delay-line W filter), with the W+H intermediate stored
// as fp16 in a __device__ scratch buffer: DRAM traffic 904 -> 678 MB.
//   kWH: x (f32) -> scratch (fp16)
//   kD : scratch (fp16) -> d_out (f32)

#define NAX   192
#define KR    6
#define NT    (2*KR + 1)        // 13 taps
#define HALO  8                 // load halo (>= KR)
#define TW    32                // strip output width
#define LC    (TW + 2*HALO)     // 48 loaded cols
#define P1    49                // smem pitch (odd -> conflict-free both ways)
#define SEGH  16                // H-phase outputs/thread
#define WLH   (SEGH + 2*KR)     // 28
#define SEGD  24
#define WLD   (SEGD + 2*KR)     // 36
#define TPBF  192
#define TPBD  256
#define VOL   (NAX * NAX * NAX)
#define NCH   8                 // 4 batch * 2 channel

// fp16 staging buffer for the W+H intermediate (113 MB; legal scratch)
__device__ __half g_mid[(size_t)NCH * VOL];

// taps T[k] = sqrt(3)*p^|k-6| as compile-time floats -> FFMA-imm in SASS (rt=1)
#define DECL_TAPS const float T[NT] = { \
     6.4102556e-04f, -2.3923386e-03f,  8.9283341e-03f, -3.3320997e-02f, \
     1.2435565e-01f, -4.6410161e-01f,  1.7320508e+00f, -4.6410161e-01f, \
     1.2435565e-01f, -3.3320997e-02f,  8.9283341e-03f, -2.3923386e-03f, \
     6.4102556e-04f }

__device__ __forceinline__ int mirror_idx(int i) {
    i = (i < 0) ? (-1 - i) : i;                  // half-sample left reflect
    return (i >= NAX) ? (2 * NAX - 1 - i) : i;   // half-sample right reflect
}

// ---------------------------------------------------------------------------
// Fused W+H pass, one 192 x 32 strip per block, one 192x49 smem buffer.
// Phase 1: load 192x48 (w-halo mirrored), 48 independent coalesced LDG.
// Phase 2: W filter in place (thread = row, 13-deep register delay line).
// Phase 3: H filter on cols [8,40), fp16 coalesced STG to g_mid.
// ---------------------------------------------------------------------------
__global__ __launch_bounds__(TPBF, 5) void kWH(const float* __restrict__ in) {
    extern __shared__ float s[];   // [192][P1]

    const int tid   = threadIdx.x;              // 0..191
    const int strip = blockIdx.x % (NAX / TW);  // 6 strips; adjacent -> L2 halo reuse
    const int slice = blockIdx.x / (NAX / TW);
    const int base  = slice * (NAX * NAX);
    const int wbase = strip * TW;

    // ---- load 192 x 48 (coalesced LDG, independent -> high MLP)
#pragma unroll
    for (int k = 0; k < (NAX * LC) / TPBF; ++k) {   // 48 iterations
        int i   = tid + TPBF * k;
        int row = i / LC;
        int c   = i - row * LC;
        s[row * P1 + c] = in[base + row * NAX + mirror_idx(wbase - HALO + c)];
    }
    __syncthreads();

    DECL_TAPS;

    // ---- W filter in place: thread owns row `tid`.
    // Output j needs smem cols (j+2)..(j+14); write col j+8 after reading
    // col j+14 -> later iterations read smem only at cols >= j+15. Safe.
    {
        float* rp = &s[tid * P1];   // lanes: stride-49 -> conflict-free
        float win[NT];
#pragma unroll
        for (int m = 0; m < NT - 1; ++m) win[m] = rp[2 + m];   // cols 2..13
#pragma unroll
        for (int j = 0; j < TW; ++j) {
            win[NT - 1] = rp[j + HALO + KR];                   // col j+14
            float acc = 0.0f;
#pragma unroll
            for (int k = 0; k < NT; ++k) acc = fmaf(T[k], win[k], acc);
            rp[j + HALO] = acc;                                // col j+8
#pragma unroll
            for (int m = 0; m < NT - 1; ++m) win[m] = win[m + 1];  // reg rotate
        }
    }
    __syncthreads();

    // ---- H filter: 384 tasks = (w 0..31) x (hseg 0..11 of 16 outputs)
#pragma unroll
    for (int r = 0; r < 2; ++r) {
        const int t    = tid + TPBF * r;
        const int w    = t & (TW - 1);
        const int hseg = t >> 5;                 // 0..11
        const int h0   = hseg * SEGH;

        float win[WLH];
#pragma unroll
        for (int m = 0; m < WLH; ++m)
            win[m] = s[mirror_idx(h0 - KR + m) * P1 + HALO + w];  // lane = w -> conflict-free

        __half* o = g_mid + base + wbase + w;
#pragma unroll
        for (int j = 0; j < SEGH; ++j) {
            float acc = 0.0f;
#pragma unroll
            for (int k = 0; k < NT; ++k) acc = fmaf(T[k], win[j + k], acc);
            o[(h0 + j) * NAX] = __float2half_rn(acc);   // 64B coalesced per j
        }
    }
}

// ---------------------------------------------------------------------------
// D pass (stride 192*192): g_mid (fp16) -> out (f32). Tile: 192(d) x 32(w).
// ---------------------------------------------------------------------------
__global__ __launch_bounds__(TPBD, 5) void kD(float* __restrict__ out) {
    __shared__ float s[NAX][32];
    const int tid = threadIdx.x;
    const int c   = blockIdx.x % (NAX / 32);
    const int tt  = blockIdx.x / (NAX / 32);
    const int b   = tt / NAX;
    const int hh  = tt % NAX;
    const int base = b * VOL + hh * NAX + c * 32;

    const int w  = tid & 31;
    const int a4 = tid >> 5;
    const __half* src = g_mid + base + w;
#pragma unroll
    for (int k = 0; k < NAX / 8; ++k)   // 24 outstanding LDG.16/thread
        s[a4 + 8 * k][w] = __half2float(src[(a4 + 8 * k) * (NAX * NAX)]);
    __syncthreads();

    DECL_TAPS;
    const int a0 = (tid >> 5) * SEGD;
    float win[WLD];
#pragma unroll
    for (int m = 0; m < WLD; ++m)
        win[m] = s[mirror_idx(a0 - KR + m)][w];

#pragma unroll
    for (int j = 0; j < SEGD; ++j) {
        float acc = 0.0f;
#pragma unroll
        for (int k = 0; k < NT; ++k) acc = fmaf(T[k], win[j + k], acc);
        out[base + (a0 + j) * (NAX * NAX) + w] = acc;     // 128B coalesced per j
    }
}

extern "C" void kernel_launch(void* const* d_in, const int* in_sizes, int n_in,
                              void* d_out, int out_size) {
    const float* x = (const float*)d_in[0];
    float* y = (float*)d_out;

    const int smemWH = NAX * P1 * (int)sizeof(float);   // 37632 B

    static int attr_set = 0;
    if (!attr_set) {
        cudaFuncSetAttribute(kWH, cudaFuncAttributeMaxDynamicSharedMemorySize, smemWH);
        attr_set = 1;
    }

    const int gridWH = NCH * NAX * (NAX / TW);   // 9216 blocks
    const int gridD  = NCH * NAX * (NAX / 32);   // 9216 blocks

    kWH<<<gridWH, TPBF, smemWH>>>(x);   // W+H fused: x -> g_mid (fp16)
    kD<<<gridD, TPBD>>>(y);             // D axis: g_mid -> d_out (f32)
}

// round 15
// speedup vs baseline: 1.2272x; 1.0110x over previous
#include <cuda_runtime.h>
#include <cuda_fp16.h>

// Cubic B-spline prefilter (Unser), DCT-II mirror boundaries, as a truncated
// symmetric FIR: h[k] = sqrt(3) * p^|k|, p = sqrt(3)-2, radius 6 (13 taps).
// R14 structure (best): W+H fused with in-place register-delay-line W filter,
// fp16 staging buffer for the intermediate (DRAM 904 -> ~680 MB, partially
// L2-resident). Single change vs R14: kD at occupancy 6 (regs 40 <= cap 42).
//   kWH: x (f32) -> g_mid (fp16)
//   kD : g_mid (fp16) -> d_out (f32)

#define NAX   192
#define KR    6
#define NT    (2*KR + 1)        // 13 taps
#define HALO  8                 // load halo (>= KR)
#define TW    32                // strip output width
#define LC    (TW + 2*HALO)     // 48 loaded cols
#define P1    49                // smem pitch (odd -> conflict-free both ways)
#define SEGH  16                // H-phase outputs/thread
#define WLH   (SEGH + 2*KR)     // 28
#define SEGD  24
#define WLD   (SEGD + 2*KR)     // 36
#define TPBF  192
#define TPBD  256
#define VOL   (NAX * NAX * NAX)
#define NCH   8                 // 4 batch * 2 channel

// fp16 staging buffer for the W+H intermediate (113 MB; legal scratch)
__device__ __half g_mid[(size_t)NCH * VOL];

// taps T[k] = sqrt(3)*p^|k-6| as compile-time floats -> FFMA-imm in SASS (rt=1)
#define DECL_TAPS const float T[NT] = { \
     6.4102556e-04f, -2.3923386e-03f,  8.9283341e-03f, -3.3320997e-02f, \
     1.2435565e-01f, -4.6410161e-01f,  1.7320508e+00f, -4.6410161e-01f, \
     1.2435565e-01f, -3.3320997e-02f,  8.9283341e-03f, -2.3923386e-03f, \
     6.4102556e-04f }

__device__ __forceinline__ int mirror_idx(int i) {
    i = (i < 0) ? (-1 - i) : i;                  // half-sample left reflect
    return (i >= NAX) ? (2 * NAX - 1 - i) : i;   // half-sample right reflect
}

// ---------------------------------------------------------------------------
// Fused W+H pass, one 192 x 32 strip per block, one 192x49 smem buffer.
// Phase 1: load 192x48 (w-halo mirrored), 48 independent coalesced LDG.
// Phase 2: W filter in place (thread = row, 13-deep register delay line).
// Phase 3: H filter on cols [8,40), fp16 coalesced STG to g_mid.
// ---------------------------------------------------------------------------
__global__ __launch_bounds__(TPBF, 5) void kWH(const float* __restrict__ in) {
    extern __shared__ float s[];   // [192][P1]

    const int tid   = threadIdx.x;              // 0..191
    const int strip = blockIdx.x % (NAX / TW);  // 6 strips; adjacent -> L2 halo reuse
    const int slice = blockIdx.x / (NAX / TW);
    const int base  = slice * (NAX * NAX);
    const int wbase = strip * TW;

    // ---- load 192 x 48 (coalesced LDG, independent -> high MLP)
#pragma unroll
    for (int k = 0; k < (NAX * LC) / TPBF; ++k) {   // 48 iterations
        int i   = tid + TPBF * k;
        int row = i / LC;
        int c   = i - row * LC;
        s[row * P1 + c] = in[base + row * NAX + mirror_idx(wbase - HALO + c)];
    }
    __syncthreads();

    DECL_TAPS;

    // ---- W filter in place: thread owns row `tid`.
    // Output j needs smem cols (j+2)..(j+14); write col j+8 after reading
    // col j+14 -> later iterations read smem only at cols >= j+15. Safe.
    {
        float* rp = &s[tid * P1];   // lanes: stride-49 -> conflict-free
        float win[NT];
#pragma unroll
        for (int m = 0; m < NT - 1; ++m) win[m] = rp[2 + m];   // cols 2..13
#pragma unroll
        for (int j = 0; j < TW; ++j) {
            win[NT - 1] = rp[j + HALO + KR];                   // col j+14
            float acc = 0.0f;
#pragma unroll
            for (int k = 0; k < NT; ++k) acc = fmaf(T[k], win[k], acc);
            rp[j + HALO] = acc;                                // col j+8
#pragma unroll
            for (int m = 0; m < NT - 1; ++m) win[m] = win[m + 1];  // reg rotate
        }
    }
    __syncthreads();

    // ---- H filter: 384 tasks = (w 0..31) x (hseg 0..11 of 16 outputs)
#pragma unroll
    for (int r = 0; r < 2; ++r) {
        const int t    = tid + TPBF * r;
        const int w    = t & (TW - 1);
        const int hseg = t >> 5;                 // 0..11
        const int h0   = hseg * SEGH;

        float win[WLH];
#pragma unroll
        for (int m = 0; m < WLH; ++m)
            win[m] = s[mirror_idx(h0 - KR + m) * P1 + HALO + w];  // lane = w -> conflict-free

        __half* o = g_mid + base + wbase + w;
#pragma unroll
        for (int j = 0; j < SEGH; ++j) {
            float acc = 0.0f;
#pragma unroll
            for (int k = 0; k < NT; ++k) acc = fmaf(T[k], win[j + k], acc);
            o[(h0 + j) * NAX] = __float2half_rn(acc);   // 64B coalesced per j
        }
    }
}

// ---------------------------------------------------------------------------
// D pass (stride 192*192): g_mid (fp16) -> out (f32). Tile: 192(d) x 32(w).
// Occupancy 6 (regs 40 <= cap 42; smem 150 KB/SM).
// ---------------------------------------------------------------------------
__global__ __launch_bounds__(TPBD, 6) void kD(float* __restrict__ out) {
    __shared__ float s[NAX][32];
    const int tid = threadIdx.x;
    const int c   = blockIdx.x % (NAX / 32);
    const int tt  = blockIdx.x / (NAX / 32);
    const int b   = tt / NAX;
    const int hh  = tt % NAX;
    const int base = b * VOL + hh * NAX + c * 32;

    const int w  = tid & 31;
    const int a4 = tid >> 5;
    const __half* src = g_mid + base + w;
#pragma unroll
    for (int k = 0; k < NAX / 8; ++k)   // 24 outstanding LDG.16/thread
        s[a4 + 8 * k][w] = __half2float(src[(a4 + 8 * k) * (NAX * NAX)]);
    __syncthreads();

    DECL_TAPS;
    const int a0 = (tid >> 5) * SEGD;
    float win[WLD];
#pragma unroll
    for (int m = 0; m < WLD; ++m)
        win[m] = s[mirror_idx(a0 - KR + m)][w];

#pragma unroll
    for (int j = 0; j < SEGD; ++j) {
        float acc = 0.0f;
#pragma unroll
        for (int k = 0; k < NT; ++k) acc = fmaf(T[k], win[j + k], acc);
        out[base + (a0 + j) * (NAX * NAX) + w] = acc;     // 128B coalesced per j
    }
}

extern "C" void kernel_launch(void* const* d_in, const int* in_sizes, int n_in,
                              void* d_out, int out_size) {
    const float* x = (const float*)d_in[0];
    float* y = (float*)d_out;

    const int smemWH = NAX * P1 * (int)sizeof(float);   // 37632 B

    static int attr_set = 0;
    if (!attr_set) {
        cudaFuncSetAttribute(kWH, cudaFuncAttributeMaxDynamicSharedMemorySize, smemWH);
        attr_set = 1;
    }

    const int gridWH = NCH * NAX * (NAX / TW);   // 9216 blocks
    const int gridD  = NCH * NAX * (NAX / 32);   // 9216 blocks

    kWH<<<gridWH, TPBF, smemWH>>>(x);   // W+H fused: x -> g_mid (fp16)
    kD<<<gridD, TPBD>>>(y);             // D axis: g_mid -> d_out (f32)
}